// round 8
// baseline (speedup 1.0000x reference)
#include <cuda_runtime.h>
#include <cuda_bf16.h>
#include <math.h>

#define NN 40000
#define EE 600000
#define HC 128          // H*C
#define FUSED 384
#define ROLES 11        // 4 cat0 + 4 cat1 + 2 cat2 + 1 scatter
#define RPB 431         // ranks per role
#define P1GRID (ROLES * RPB)

typedef unsigned long long u64;

// ---------------- scratch (device globals; no allocation allowed) -------------
__device__ __align__(16) float g_xw[3][NN * HC];   // transformed features
__device__ __align__(8)  float g_as[3][NN * 2];    // a_src per node/head
__device__ __align__(8)  float g_ad[3][NN * 2];    // a_dst per node/head
__device__ int        g_deg[3][NN];
__device__ int        g_rowptr[3][NN + 1];
__device__ int        g_cur[3][NN];
__device__ int        g_srt[3][EE];                // src ids sorted by dst
__device__ ulonglong2 g_Wq[3][4096];               // quad-packed W (k-quads)
__device__ ulonglong2 g_Wc1q[12288];               // quad-packed Wc1

__device__ __forceinline__ void ffma2(u64& acc, u64 a, u64 b)
{
    asm("fma.rn.f32x2 %0, %1, %2, %0;" : "+l"(acc) : "l"(a), "l"(b));
}
__device__ __forceinline__ float unpack_sum(u64 v)
{
    float lo, hi;
    asm("mov.b64 {%0,%1}, %2;" : "=f"(lo), "=f"(hi) : "l"(v));
    return lo + hi;
}
__device__ __forceinline__ u64 packf2(float lo, float hi)
{
    return ((u64)__float_as_uint(hi) << 32) | (u64)__float_as_uint(lo);
}

// ---------------- k0: weight pre-pack + degree histogram ----------------------
__global__ void __launch_bounds__(256)
pack_hist_kernel(const float* __restrict__ W0, const float* __restrict__ W1,
                 const float* __restrict__ W2, const float* __restrict__ Wc1,
                 const int* __restrict__ e0, const int* __restrict__ e1,
                 const int* __restrict__ e2)
{
    if (blockIdx.x < 88) {      // pack role
        const int i = blockIdx.x * 256 + threadIdx.x;
        const float* W; ulonglong2* dst; int base;
        if      (i <  4096) { W = W0;  dst = g_Wq[0]; base = i; }
        else if (i <  8192) { W = W1;  dst = g_Wq[1]; base = i - 4096; }
        else if (i < 10240) { W = W2;  dst = g_Wq[2]; base = i - 8192; }
        else if (i < 22528) { W = Wc1; dst = g_Wc1q;  base = i - 10240; }
        else return;
        const int c = base & 127, k4 = base >> 7;
        const float v0 = W[(4 * k4 + 0) * 128 + c];
        const float v1 = W[(4 * k4 + 1) * 128 + c];
        const float v2 = W[(4 * k4 + 2) * 128 + c];
        const float v3 = W[(4 * k4 + 3) * 128 + c];
        ulonglong2 q; q.x = packf2(v0, v1); q.y = packf2(v2, v3);
        dst[base] = q;
    } else {                    // histogram role
        const int g = (blockIdx.x - 88) * 256 + threadIdx.x;
        if (g >= 3 * EE) return;
        const int cat = g / EE, le = g - cat * EE;
        const int* ei = cat == 0 ? e0 : (cat == 1 ? e1 : e2);
        atomicAdd(&g_deg[cat][ei[EE + le]], 1);
    }
}

// ---------------- k1: CSR scan -------------------------------------------------
__global__ void scan3_kernel()
{
    const int cat = blockIdx.x;
    const int* deg = g_deg[cat];
    int* rowptr = g_rowptr[cat];
    int* cur = g_cur[cat];
    const int t = threadIdx.x;              // 0..1023
    const int CH = (NN + 1023) / 1024;      // 40
    const int lo = t * CH;
    const int hi = min(lo + CH, NN);
    int s = 0;
    for (int i = lo; i < hi; i++) s += deg[i];
    __shared__ int wsum[32];
    const int lane = t & 31, wid = t >> 5;
    int v = s;
#pragma unroll
    for (int o = 1; o < 32; o <<= 1) {
        const int u = __shfl_up_sync(0xFFFFFFFFu, v, o);
        if (lane >= o) v += u;
    }
    if (lane == 31) wsum[wid] = v;
    __syncthreads();
    if (wid == 0) {
        int u = wsum[lane];
#pragma unroll
        for (int o = 1; o < 32; o <<= 1) {
            const int t2 = __shfl_up_sync(0xFFFFFFFFu, u, o);
            if (lane >= o) u += t2;
        }
        wsum[lane] = u;
    }
    __syncthreads();
    int run = v - s + (wid ? wsum[wid - 1] : 0);
    for (int i = lo; i < hi; i++) {
        rowptr[i] = run; cur[i] = run; run += deg[i];
    }
    if (t == 1023) rowptr[NN] = run;
}

// ---------------- GEMM body: xw = x @ W + fused attention dots ---------------
template <int DIN>
__device__ __forceinline__ void gemm_body(const float* __restrict__ x,
                                          const ulonglong2* __restrict__ Wq,
                                          const float* __restrict__ att_s,
                                          const float* __restrict__ att_d,
                                          float* __restrict__ xw,
                                          float* __restrict__ as_,
                                          float* __restrict__ ad_,
                                          int r2, int stride, float* xs,
                                          float (*redbuf)[8][2])
{
    const int c = threadIdx.x;              // 0..127 output column
    const float vs = att_s[c];
    const float vd = att_d[c];
    const int w = c >> 5;
    for (int g = r2; g < NN / 8; g += stride) {
        const int n0 = g * 8;
        __syncthreads();
        for (int i = c; i < 8 * DIN / 4; i += 128)
            reinterpret_cast<float4*>(xs)[i] =
                reinterpret_cast<const float4*>(x + n0 * DIN)[i];
        __syncthreads();
        u64 acc2[8];
#pragma unroll
        for (int r = 0; r < 8; r++) acc2[r] = 0ull;
#pragma unroll 4
        for (int k4 = 0; k4 < DIN / 4; k4++) {
            const ulonglong2 wp = Wq[k4 * 128 + c];
#pragma unroll
            for (int r = 0; r < 8; r++) {
                const ulonglong2 a =
                    *reinterpret_cast<const ulonglong2*>(&xs[r * DIN + 4 * k4]);
                ffma2(acc2[r], a.x, wp.x);
                ffma2(acc2[r], a.y, wp.y);
            }
        }
#pragma unroll
        for (int r = 0; r < 8; r++) {
            const float accr = unpack_sum(acc2[r]);
            xw[(n0 + r) * HC + c] = accr;
            float ps = accr * vs, pd = accr * vd;
#pragma unroll
            for (int o = 16; o; o >>= 1) {
                ps += __shfl_down_sync(0xFFFFFFFFu, ps, o);
                pd += __shfl_down_sync(0xFFFFFFFFu, pd, o);
            }
            if ((c & 31) == 0) { redbuf[w][r][0] = ps; redbuf[w][r][1] = pd; }
        }
        __syncthreads();
        if (c < 16) {               // c encodes (r, h)
            const int r = c >> 1, h = c & 1;
            as_[(n0 + r) * 2 + h] = redbuf[2 * h][r][0] + redbuf[2 * h + 1][r][0];
            ad_[(n0 + r) * 2 + h] = redbuf[2 * h][r][1] + redbuf[2 * h + 1][r][1];
        }
    }
}

// ---------------- k2: 3 GEMMs + CSR scatter in one heterogeneous grid ---------
__global__ void __launch_bounds__(128)
phase1_kernel(const float* __restrict__ x0, const float* __restrict__ x1,
              const float* __restrict__ x2,
              const float* __restrict__ s0, const float* __restrict__ s1,
              const float* __restrict__ s2,
              const float* __restrict__ t0, const float* __restrict__ t1,
              const float* __restrict__ t2,
              const int* __restrict__ e0, const int* __restrict__ e1,
              const int* __restrict__ e2)
{
    __shared__ __align__(16) float xs[8 * 128];
    __shared__ float redbuf[4][8][2];
    const int role = blockIdx.x % ROLES;
    const int rank = blockIdx.x / ROLES;
    if (role < 4)
        gemm_body<128>(x0, g_Wq[0], s0, t0, g_xw[0], g_as[0], g_ad[0],
                       role * RPB + rank, 4 * RPB, xs, redbuf);
    else if (role < 8)
        gemm_body<128>(x1, g_Wq[1], s1, t1, g_xw[1], g_as[1], g_ad[1],
                       (role - 4) * RPB + rank, 4 * RPB, xs, redbuf);
    else if (role < 10)
        gemm_body<64>(x2, g_Wq[2], s2, t2, g_xw[2], g_as[2], g_ad[2],
                      (role - 8) * RPB + rank, 2 * RPB, xs, redbuf);
    else {                      // scatter role: build g_srt (independent of GEMM)
        const int stride = RPB * 128;
        for (int g = rank * 128 + threadIdx.x; g < 3 * EE; g += stride) {
            const int cat = g / EE, le = g - cat * EE;
            const int* ei = cat == 0 ? e0 : (cat == 1 ? e1 : e2);
            const int pos = atomicAdd(&g_cur[cat][ei[EE + le]], 1);
            g_srt[cat][pos] = ei[le];
        }
    }
}

// ---------------- k3: fused gather + softmax + ELU + MLP (8 nodes/block) ------
__global__ void __launch_bounds__(256)
gather_mlp_kernel(const float* __restrict__ b0, const float* __restrict__ b1,
                  const float* __restrict__ b2,
                  const float* __restrict__ bc1, const float* __restrict__ Wc2,
                  const float* __restrict__ bc2, float* __restrict__ out)
{
    __shared__ __align__(16) float hs[8 * FUSED];
    __shared__ __align__(16) int4 recs[8][32];     // per-warp edge-record stage
    __shared__ float pacc[2][8][128];              // split-K partial sums
    __shared__ float redm[8][4];
    const int tid = threadIdx.x, wid = tid >> 5, lane = tid & 31;
    const int n0 = blockIdx.x * 8;
    const int dst = n0 + wid;
    const int h = lane >> 4;                  // lanes 0-15 head0, 16-31 head1

    for (int cat = 0; cat < 3; cat++) {
        const float* as_ = g_as[cat];
        const float* xw  = g_xw[cat];
        const int*   srt = g_srt[cat];
        const float* bias = cat == 0 ? b0 : (cat == 1 ? b1 : b2);

        const float2 ad2 = *reinterpret_cast<const float2*>(&g_ad[cat][dst * 2]);
        const float2 as2 = __ldg(reinterpret_cast<const float2*>(as_) + dst);
        float t0 = as2.x + ad2.x; t0 = t0 > 0.f ? t0 : 0.2f * t0;
        float t1 = as2.y + ad2.y; t1 = t1 > 0.f ? t1 : 0.2f * t1;
        const float exs0 = __expf(t0), exs1 = __expf(t1);
        float d0 = (lane == 0) ? exs0 : 0.f;
        float d1 = (lane == 0) ? exs1 : 0.f;
        const float exself = h ? exs1 : exs0;
        float4 v = __ldg(&reinterpret_cast<const float4*>(xw + (size_t)dst * HC)[lane]);
        float4 acc = make_float4(v.x * exself, v.y * exself, v.z * exself, v.w * exself);

        const int start = __ldg(&g_rowptr[cat][dst]);
        const int end   = __ldg(&g_rowptr[cat][dst + 1]);
        for (int p = start; p < end; p += 32) {
            const int n = min(32, end - p);
            const int mysrc = (lane < n) ? __ldg(srt + p + lane) : 0;
            const float2 a = __ldg(reinterpret_cast<const float2*>(as_) + mysrc);
            float u0 = a.x + ad2.x; u0 = u0 > 0.f ? u0 : 0.2f * u0;
            float u1 = a.y + ad2.y; u1 = u1 > 0.f ? u1 : 0.2f * u1;
            const float x0 = __expf(u0), x1 = __expf(u1);
            if (lane < n) { d0 += x0; d1 += x1; }
            recs[wid][lane] = make_int4(mysrc, __float_as_int(x0),
                                        __float_as_int(x1), 0);
            __syncwarp();
#pragma unroll 4
            for (int i = 0; i < n; i++) {
                const int4 rec = recs[wid][i];         // uniform LDS -> broadcast
                const float exh = h ? __int_as_float(rec.z) : __int_as_float(rec.y);
                const float4 u = __ldg(&reinterpret_cast<const float4*>(
                                           xw + (size_t)rec.x * HC)[lane]);
                acc.x += u.x * exh; acc.y += u.y * exh;
                acc.z += u.z * exh; acc.w += u.w * exh;
            }
            __syncwarp();
        }
#pragma unroll
        for (int o = 16; o; o >>= 1) {
            d0 += __shfl_xor_sync(0xFFFFFFFFu, d0, o);
            d1 += __shfl_xor_sync(0xFFFFFFFFu, d1, o);
        }
        const float inv = __fdividef(1.f, h ? d1 : d0);
        const int col = lane * 4;
        float4 o;
        o.x = acc.x * inv + bias[col + 0]; o.x = o.x > 0.f ? o.x : expm1f(o.x);
        o.y = acc.y * inv + bias[col + 1]; o.y = o.y > 0.f ? o.y : expm1f(o.y);
        o.z = acc.z * inv + bias[col + 2]; o.z = o.z > 0.f ? o.z : expm1f(o.z);
        o.w = acc.w * inv + bias[col + 3]; o.w = o.w > 0.f ? o.w : expm1f(o.w);
        *reinterpret_cast<float4*>(&hs[wid * FUSED + cat * HC + col]) = o;
    }
    __syncthreads();

    // ---- MLP, split-K: group g covers k4 in [48g, 48g+48), all 8 rows -------
    const int j = tid & 127;
    const int grp = tid >> 7;
    u64 acc2[8];
#pragma unroll
    for (int r = 0; r < 8; r++) acc2[r] = 0ull;
    const int k4lo = grp * 48;
#pragma unroll 4
    for (int kk = 0; kk < 48; kk++) {
        const int k4 = k4lo + kk;
        const ulonglong2 wp = g_Wc1q[k4 * 128 + j];
#pragma unroll
        for (int r = 0; r < 8; r++) {
            const ulonglong2 a = *reinterpret_cast<const ulonglong2*>(
                &hs[r * FUSED + 4 * k4]);
            ffma2(acc2[r], a.x, wp.x);
            ffma2(acc2[r], a.y, wp.y);
        }
    }
#pragma unroll
    for (int r = 0; r < 8; r++) pacc[grp][r][j] = unpack_sum(acc2[r]);
    __syncthreads();

    // rows grp*4 .. grp*4+3 finalized by group grp (combine + relu + Wc2 dot)
    const float w2c = Wc2[j];
    const float b1c = bc1[j];
#pragma unroll
    for (int lr = 0; lr < 4; lr++) {
        const int row = grp * 4 + lr;
        float hv = pacc[0][row][j] + pacc[1][row][j] + b1c;
        hv = fmaxf(hv, 0.f);
        float p = hv * w2c;
#pragma unroll
        for (int o = 16; o; o >>= 1) p += __shfl_down_sync(0xFFFFFFFFu, p, o);
        if (lane == 0) redm[wid][lr] = p;
    }
    __syncthreads();
    if (tid < 8) {
        const int g = tid >> 2, lr = tid & 3;
        out[n0 + tid] = redm[4 * g + 0][lr] + redm[4 * g + 1][lr] +
                        redm[4 * g + 2][lr] + redm[4 * g + 3][lr] + bc2[0];
    }
}

// ---------------- host orchestration ------------------------------------------
extern "C" void kernel_launch(void* const* d_in, const int* in_sizes, int n_in,
                              void* d_out, int out_size)
{
    const float* x[3];  const int* ei[3];  const float* W[3];
    const float* atts[3]; const float* attd[3]; const float* bias[3];
    for (int i = 0; i < 3; i++) {
        x[i]    = (const float*)d_in[6 * i + 0];
        ei[i]   = (const int*)  d_in[6 * i + 1];
        W[i]    = (const float*)d_in[6 * i + 2];
        atts[i] = (const float*)d_in[6 * i + 3];
        attd[i] = (const float*)d_in[6 * i + 4];
        bias[i] = (const float*)d_in[6 * i + 5];
    }
    const float* Wc1 = (const float*)d_in[18];
    const float* bc1 = (const float*)d_in[19];
    const float* Wc2 = (const float*)d_in[20];
    const float* bc2 = (const float*)d_in[21];
    float* out = (float*)d_out;

    int* p_deg;
    cudaGetSymbolAddress((void**)&p_deg, g_deg);
    cudaMemsetAsync(p_deg, 0, sizeof(int) * 3 * NN);

    // k0: pack + histogram
    pack_hist_kernel<<<88 + (3 * EE + 255) / 256, 256>>>(
        W[0], W[1], W[2], Wc1, ei[0], ei[1], ei[2]);

    // k1: scan
    scan3_kernel<<<3, 1024>>>();

    // k2: GEMMs + scatter
    phase1_kernel<<<P1GRID, 128>>>(x[0], x[1], x[2],
                                   atts[0], atts[1], atts[2],
                                   attd[0], attd[1], attd[2],
                                   ei[0], ei[1], ei[2]);

    // k3: gather + MLP  (lands in the ncu capture slot)
    gather_mlp_kernel<<<NN / 8, 256>>>(bias[0], bias[1], bias[2],
                                       bc1, Wc2, bc2, out);
}

// round 9
// speedup vs baseline: 1.5946x; 1.5946x over previous
#include <cuda_runtime.h>
#include <cuda_bf16.h>
#include <math.h>

#define NN 40000
#define EE 600000
#define HC 128          // H*C
#define FUSED 384
#define ROLES 11        // 4 cat0 + 4 cat1 + 2 cat2 + 1 scatter
#define RPB 431         // ranks per role
#define P1GRID (ROLES * RPB)

typedef unsigned long long u64;

// ---------------- scratch (device globals; no allocation allowed) -------------
__device__ __align__(16) float g_xw[3][NN * HC];   // transformed features
__device__ __align__(8)  float g_as[3][NN * 2];    // a_src per node/head
__device__ __align__(8)  float g_ad[3][NN * 2];    // a_dst per node/head
__device__ int        g_deg[3][NN];
__device__ int        g_rowptr[3][NN + 1];
__device__ int        g_cur[3][NN];
__device__ int        g_srt[3][EE];                // src ids sorted by dst
__device__ ulonglong2 g_Wq[3][4096];               // quad-packed W (k-quads)
__device__ ulonglong2 g_Wc1q[12288];               // quad-packed Wc1

__device__ __forceinline__ void ffma2(u64& acc, u64 a, u64 b)
{
    asm("fma.rn.f32x2 %0, %1, %2, %0;" : "+l"(acc) : "l"(a), "l"(b));
}
__device__ __forceinline__ float unpack_sum(u64 v)
{
    float lo, hi;
    asm("mov.b64 {%0,%1}, %2;" : "=f"(lo), "=f"(hi) : "l"(v));
    return lo + hi;
}
__device__ __forceinline__ u64 packf2(float lo, float hi)
{
    return ((u64)__float_as_uint(hi) << 32) | (u64)__float_as_uint(lo);
}

// ---------------- k0: weight pre-pack + degree histogram ----------------------
__global__ void __launch_bounds__(256)
pack_hist_kernel(const float* __restrict__ W0, const float* __restrict__ W1,
                 const float* __restrict__ W2, const float* __restrict__ Wc1,
                 const int* __restrict__ e0, const int* __restrict__ e1,
                 const int* __restrict__ e2)
{
    if (blockIdx.x < 88) {      // pack role
        const int i = blockIdx.x * 256 + threadIdx.x;
        const float* W; ulonglong2* dst; int base;
        if      (i <  4096) { W = W0;  dst = g_Wq[0]; base = i; }
        else if (i <  8192) { W = W1;  dst = g_Wq[1]; base = i - 4096; }
        else if (i < 10240) { W = W2;  dst = g_Wq[2]; base = i - 8192; }
        else if (i < 22528) { W = Wc1; dst = g_Wc1q;  base = i - 10240; }
        else return;
        const int c = base & 127, k4 = base >> 7;
        const float v0 = W[(4 * k4 + 0) * 128 + c];
        const float v1 = W[(4 * k4 + 1) * 128 + c];
        const float v2 = W[(4 * k4 + 2) * 128 + c];
        const float v3 = W[(4 * k4 + 3) * 128 + c];
        ulonglong2 q; q.x = packf2(v0, v1); q.y = packf2(v2, v3);
        dst[base] = q;
    } else {                    // histogram role
        const int g = (blockIdx.x - 88) * 256 + threadIdx.x;
        if (g >= 3 * EE) return;
        const int cat = g / EE, le = g - cat * EE;
        const int* ei = cat == 0 ? e0 : (cat == 1 ? e1 : e2);
        atomicAdd(&g_deg[cat][ei[EE + le]], 1);
    }
}

// ---------------- k1: CSR scan -------------------------------------------------
__global__ void scan3_kernel()
{
    const int cat = blockIdx.x;
    const int* deg = g_deg[cat];
    int* rowptr = g_rowptr[cat];
    int* cur = g_cur[cat];
    const int t = threadIdx.x;              // 0..1023
    const int CH = (NN + 1023) / 1024;      // 40
    const int lo = t * CH;
    const int hi = min(lo + CH, NN);
    int s = 0;
    for (int i = lo; i < hi; i++) s += deg[i];
    __shared__ int wsum[32];
    const int lane = t & 31, wid = t >> 5;
    int v = s;
#pragma unroll
    for (int o = 1; o < 32; o <<= 1) {
        const int u = __shfl_up_sync(0xFFFFFFFFu, v, o);
        if (lane >= o) v += u;
    }
    if (lane == 31) wsum[wid] = v;
    __syncthreads();
    if (wid == 0) {
        int u = wsum[lane];
#pragma unroll
        for (int o = 1; o < 32; o <<= 1) {
            const int t2 = __shfl_up_sync(0xFFFFFFFFu, u, o);
            if (lane >= o) u += t2;
        }
        wsum[lane] = u;
    }
    __syncthreads();
    int run = v - s + (wid ? wsum[wid - 1] : 0);
    for (int i = lo; i < hi; i++) {
        rowptr[i] = run; cur[i] = run; run += deg[i];
    }
    if (t == 1023) rowptr[NN] = run;
}

// ---------------- GEMM body: xw = x @ W + fused attention dots ---------------
template <int DIN>
__device__ __forceinline__ void gemm_body(const float* __restrict__ x,
                                          const ulonglong2* __restrict__ Wq,
                                          const float* __restrict__ att_s,
                                          const float* __restrict__ att_d,
                                          float* __restrict__ xw,
                                          float* __restrict__ as_,
                                          float* __restrict__ ad_,
                                          int r2, int stride, float* xs,
                                          float (*redbuf)[8][2])
{
    const int c = threadIdx.x;              // 0..127 output column
    const float vs = att_s[c];
    const float vd = att_d[c];
    const int w = c >> 5;
    for (int g = r2; g < NN / 8; g += stride) {
        const int n0 = g * 8;
        __syncthreads();
        for (int i = c; i < 8 * DIN / 4; i += 128)
            reinterpret_cast<float4*>(xs)[i] =
                reinterpret_cast<const float4*>(x + n0 * DIN)[i];
        __syncthreads();
        u64 acc2[8];
#pragma unroll
        for (int r = 0; r < 8; r++) acc2[r] = 0ull;
#pragma unroll 4
        for (int k4 = 0; k4 < DIN / 4; k4++) {
            const ulonglong2 wp = Wq[k4 * 128 + c];
#pragma unroll
            for (int r = 0; r < 8; r++) {
                const ulonglong2 a =
                    *reinterpret_cast<const ulonglong2*>(&xs[r * DIN + 4 * k4]);
                ffma2(acc2[r], a.x, wp.x);
                ffma2(acc2[r], a.y, wp.y);
            }
        }
#pragma unroll
        for (int r = 0; r < 8; r++) {
            const float accr = unpack_sum(acc2[r]);
            xw[(n0 + r) * HC + c] = accr;
            float ps = accr * vs, pd = accr * vd;
#pragma unroll
            for (int o = 16; o; o >>= 1) {
                ps += __shfl_down_sync(0xFFFFFFFFu, ps, o);
                pd += __shfl_down_sync(0xFFFFFFFFu, pd, o);
            }
            if ((c & 31) == 0) { redbuf[w][r][0] = ps; redbuf[w][r][1] = pd; }
        }
        __syncthreads();
        if (c < 16) {               // c encodes (r, h)
            const int r = c >> 1, h = c & 1;
            as_[(n0 + r) * 2 + h] = redbuf[2 * h][r][0] + redbuf[2 * h + 1][r][0];
            ad_[(n0 + r) * 2 + h] = redbuf[2 * h][r][1] + redbuf[2 * h + 1][r][1];
        }
    }
}

// ---------------- k2: 3 GEMMs + CSR scatter in one heterogeneous grid ---------
__global__ void __launch_bounds__(128)
phase1_kernel(const float* __restrict__ x0, const float* __restrict__ x1,
              const float* __restrict__ x2,
              const float* __restrict__ s0, const float* __restrict__ s1,
              const float* __restrict__ s2,
              const float* __restrict__ t0, const float* __restrict__ t1,
              const float* __restrict__ t2,
              const int* __restrict__ e0, const int* __restrict__ e1,
              const int* __restrict__ e2)
{
    __shared__ __align__(16) float xs[8 * 128];
    __shared__ float redbuf[4][8][2];
    const int role = blockIdx.x % ROLES;
    const int rank = blockIdx.x / ROLES;
    if (role < 4)
        gemm_body<128>(x0, g_Wq[0], s0, t0, g_xw[0], g_as[0], g_ad[0],
                       role * RPB + rank, 4 * RPB, xs, redbuf);
    else if (role < 8)
        gemm_body<128>(x1, g_Wq[1], s1, t1, g_xw[1], g_as[1], g_ad[1],
                       (role - 4) * RPB + rank, 4 * RPB, xs, redbuf);
    else if (role < 10)
        gemm_body<64>(x2, g_Wq[2], s2, t2, g_xw[2], g_as[2], g_ad[2],
                      (role - 8) * RPB + rank, 2 * RPB, xs, redbuf);
    else {                      // scatter role: build g_srt (independent of GEMM)
        const int stride = RPB * 128;
        for (int g = rank * 128 + threadIdx.x; g < 3 * EE; g += stride) {
            const int cat = g / EE, le = g - cat * EE;
            const int* ei = cat == 0 ? e0 : (cat == 1 ? e1 : e2);
            const int pos = atomicAdd(&g_cur[cat][ei[EE + le]], 1);
            g_srt[cat][pos] = ei[le];
        }
    }
}

// ---------------- k3: fused gather + softmax + ELU + MLP (16 nodes/block) -----
__global__ void __launch_bounds__(256)
gather_mlp_kernel(const float* __restrict__ b0, const float* __restrict__ b1,
                  const float* __restrict__ b2,
                  const float* __restrict__ bc1, const float* __restrict__ Wc2,
                  const float* __restrict__ bc2, float* __restrict__ out)
{
    __shared__ __align__(16) float hs[16 * FUSED];
    __shared__ float redm[8][8];
    const int tid = threadIdx.x, wid = tid >> 5, lane = tid & 31;
    const int n0 = blockIdx.x * 16;
    const int h = lane >> 4;                  // lanes 0-15 head0, 16-31 head1

    // -------- gather: each warp processes rows wid and wid+8 ------------------
    for (int cat = 0; cat < 3; cat++) {
        const float* as_ = g_as[cat];
        const float* xw  = g_xw[cat];
        const int*   srt = g_srt[cat];
        const float* bias = cat == 0 ? b0 : (cat == 1 ? b1 : b2);

#pragma unroll
        for (int rep = 0; rep < 2; rep++) {
            const int row = wid + rep * 8;
            const int dst = n0 + row;

            const float2 ad2 = *reinterpret_cast<const float2*>(&g_ad[cat][dst * 2]);
            const float2 as2 = __ldg(reinterpret_cast<const float2*>(as_) + dst);
            float t0 = as2.x + ad2.x; t0 = t0 > 0.f ? t0 : 0.2f * t0;
            float t1 = as2.y + ad2.y; t1 = t1 > 0.f ? t1 : 0.2f * t1;
            const float exs0 = __expf(t0), exs1 = __expf(t1);
            float d0 = (lane == 0) ? exs0 : 0.f;
            float d1 = (lane == 0) ? exs1 : 0.f;
            const float exself = h ? exs1 : exs0;
            float4 v = __ldg(&reinterpret_cast<const float4*>(
                                 xw + (size_t)dst * HC)[lane]);
            float4 acc = make_float4(v.x * exself, v.y * exself,
                                     v.z * exself, v.w * exself);

            const int start = __ldg(&g_rowptr[cat][dst]);
            const int end   = __ldg(&g_rowptr[cat][dst + 1]);
            for (int p = start; p < end; p += 32) {
                const int n = min(32, end - p);
                const int mysrc = (lane < n) ? __ldg(srt + p + lane) : 0;
                const float2 a = __ldg(reinterpret_cast<const float2*>(as_) + mysrc);
                float u0 = a.x + ad2.x; u0 = u0 > 0.f ? u0 : 0.2f * u0;
                float u1 = a.y + ad2.y; u1 = u1 > 0.f ? u1 : 0.2f * u1;
                const float x0 = __expf(u0), x1 = __expf(u1);
                if (lane < n) { d0 += x0; d1 += x1; }
#pragma unroll 4
                for (int i = 0; i < n; i++) {
                    const int   src = __shfl_sync(0xFFFFFFFFu, mysrc, i);
                    const float xx0 = __shfl_sync(0xFFFFFFFFu, x0, i);
                    const float xx1 = __shfl_sync(0xFFFFFFFFu, x1, i);
                    const float exh = h ? xx1 : xx0;
                    const float4 u = __ldg(&reinterpret_cast<const float4*>(
                                               xw + (size_t)src * HC)[lane]);
                    acc.x += u.x * exh; acc.y += u.y * exh;
                    acc.z += u.z * exh; acc.w += u.w * exh;
                }
            }
#pragma unroll
            for (int o = 16; o; o >>= 1) {
                d0 += __shfl_xor_sync(0xFFFFFFFFu, d0, o);
                d1 += __shfl_xor_sync(0xFFFFFFFFu, d1, o);
            }
            const float inv = __fdividef(1.f, h ? d1 : d0);
            const int col = lane * 4;
            float4 o;
            o.x = acc.x * inv + bias[col + 0]; o.x = o.x > 0.f ? o.x : expm1f(o.x);
            o.y = acc.y * inv + bias[col + 1]; o.y = o.y > 0.f ? o.y : expm1f(o.y);
            o.z = acc.z * inv + bias[col + 2]; o.z = o.z > 0.f ? o.z : expm1f(o.z);
            o.w = acc.w * inv + bias[col + 3]; o.w = o.w > 0.f ? o.w : expm1f(o.w);
            *reinterpret_cast<float4*>(&hs[row * FUSED + cat * HC + col]) = o;
        }
    }
    __syncthreads();

    // ---- MLP: two 128-thread groups, each full-K over its own 8 rows ---------
    const int j = tid & 127;           // hidden unit
    const int grp = tid >> 7;          // 0 -> rows 0-7, 1 -> rows 8-15
    u64 acc2[8];
#pragma unroll
    for (int r = 0; r < 8; r++) acc2[r] = 0ull;
#pragma unroll 2
    for (int k4 = 0; k4 < FUSED / 4; k4++) {
        const ulonglong2 wp = g_Wc1q[k4 * 128 + j];
#pragma unroll
        for (int r = 0; r < 8; r++) {
            const ulonglong2 a = *reinterpret_cast<const ulonglong2*>(
                &hs[(grp * 8 + r) * FUSED + 4 * k4]);
            ffma2(acc2[r], a.x, wp.x);
            ffma2(acc2[r], a.y, wp.y);
        }
    }
    const float w2c = Wc2[j];
    const float b1c = bc1[j];
#pragma unroll
    for (int r = 0; r < 8; r++) {
        float hv = unpack_sum(acc2[r]) + b1c;
        hv = fmaxf(hv, 0.f);
        float p = hv * w2c;
#pragma unroll
        for (int o = 16; o; o >>= 1) p += __shfl_down_sync(0xFFFFFFFFu, p, o);
        if (lane == 0) redm[wid][r] = p;   // wid 0-3: rows 0-7; wid 4-7: rows 8-15
    }
    __syncthreads();
    if (tid < 16) {
        const int grp2 = tid >> 3;         // which group owns this row
        const int r = tid & 7;
        const int wbase = grp2 * 4;
        out[n0 + tid] = redm[wbase + 0][r] + redm[wbase + 1][r] +
                        redm[wbase + 2][r] + redm[wbase + 3][r] + bc2[0];
    }
}

// ---------------- host orchestration ------------------------------------------
extern "C" void kernel_launch(void* const* d_in, const int* in_sizes, int n_in,
                              void* d_out, int out_size)
{
    const float* x[3];  const int* ei[3];  const float* W[3];
    const float* atts[3]; const float* attd[3]; const float* bias[3];
    for (int i = 0; i < 3; i++) {
        x[i]    = (const float*)d_in[6 * i + 0];
        ei[i]   = (const int*)  d_in[6 * i + 1];
        W[i]    = (const float*)d_in[6 * i + 2];
        atts[i] = (const float*)d_in[6 * i + 3];
        attd[i] = (const float*)d_in[6 * i + 4];
        bias[i] = (const float*)d_in[6 * i + 5];
    }
    const float* Wc1 = (const float*)d_in[18];
    const float* bc1 = (const float*)d_in[19];
    const float* Wc2 = (const float*)d_in[20];
    const float* bc2 = (const float*)d_in[21];
    float* out = (float*)d_out;

    int* p_deg;
    cudaGetSymbolAddress((void**)&p_deg, g_deg);
    cudaMemsetAsync(p_deg, 0, sizeof(int) * 3 * NN);

    // k0: pack + histogram
    pack_hist_kernel<<<88 + (3 * EE + 255) / 256, 256>>>(
        W[0], W[1], W[2], Wc1, ei[0], ei[1], ei[2]);

    // k1: scan
    scan3_kernel<<<3, 1024>>>();

    // k2: GEMMs + scatter
    phase1_kernel<<<P1GRID, 128>>>(x[0], x[1], x[2],
                                   atts[0], atts[1], atts[2],
                                   attd[0], attd[1], attd[2],
                                   ei[0], ei[1], ei[2]);

    // k3: gather + MLP  (lands in the ncu capture slot)
    gather_mlp_kernel<<<NN / 16, 256>>>(bias[0], bias[1], bias[2],
                                        bc1, Wc2, bc2, out);
}

// round 10
// speedup vs baseline: 1.6605x; 1.0413x over previous
#include <cuda_runtime.h>
#include <cuda_fp16.h>
#include <math.h>

#define NN 40000
#define EE 600000
#define HC 128          // H*C
#define FUSED 384
#define ROLES 11        // 4 cat0 + 4 cat1 + 2 cat2 + 1 scatter
#define RPB 431         // ranks per role
#define P1GRID (ROLES * RPB)

typedef unsigned long long u64;

// ---------------- scratch (device globals; no allocation allowed) -------------
__device__ __align__(16) __half g_xw[3][NN * HC];  // transformed features (fp16)
__device__ __align__(8)  float g_as[3][NN * 2];    // a_src per node/head
__device__ __align__(8)  float g_ad[3][NN * 2];    // a_dst per node/head
__device__ int        g_deg[3][NN];
__device__ int        g_rowptr[3][NN + 1];
__device__ int        g_cur[3][NN];
__device__ int        g_srt[3][EE];                // src ids sorted by dst
__device__ ulonglong2 g_Wq[3][4096];               // quad-packed W (k-quads)
__device__ ulonglong2 g_Wc1q[12288];               // quad-packed Wc1

__device__ __forceinline__ void ffma2(u64& acc, u64 a, u64 b)
{
    asm("fma.rn.f32x2 %0, %1, %2, %0;" : "+l"(acc) : "l"(a), "l"(b));
}
__device__ __forceinline__ float unpack_sum(u64 v)
{
    float lo, hi;
    asm("mov.b64 {%0,%1}, %2;" : "=f"(lo), "=f"(hi) : "l"(v));
    return lo + hi;
}
__device__ __forceinline__ u64 packf2(float lo, float hi)
{
    return ((u64)__float_as_uint(hi) << 32) | (u64)__float_as_uint(lo);
}

// ---------------- k0: weight pre-pack ------------------------------------------
__global__ void __launch_bounds__(256)
pack_kernel(const float* __restrict__ W0, const float* __restrict__ W1,
            const float* __restrict__ W2, const float* __restrict__ Wc1)
{
    const int i = blockIdx.x * 256 + threadIdx.x;
    const float* W; ulonglong2* dst; int base;
    if      (i <  4096) { W = W0;  dst = g_Wq[0]; base = i; }
    else if (i <  8192) { W = W1;  dst = g_Wq[1]; base = i - 4096; }
    else if (i < 10240) { W = W2;  dst = g_Wq[2]; base = i - 8192; }
    else if (i < 22528) { W = Wc1; dst = g_Wc1q;  base = i - 10240; }
    else return;
    const int c = base & 127, k4 = base >> 7;
    const float v0 = W[(4 * k4 + 0) * 128 + c];
    const float v1 = W[(4 * k4 + 1) * 128 + c];
    const float v2 = W[(4 * k4 + 2) * 128 + c];
    const float v3 = W[(4 * k4 + 3) * 128 + c];
    ulonglong2 q; q.x = packf2(v0, v1); q.y = packf2(v2, v3);
    dst[base] = q;
}

// ---------------- k1: degree histogram -----------------------------------------
__global__ void __launch_bounds__(256)
hist_kernel(const int* __restrict__ e0, const int* __restrict__ e1,
            const int* __restrict__ e2)
{
    const int g = blockIdx.x * 256 + threadIdx.x;
    if (g >= 3 * EE) return;
    const int cat = g / EE, le = g - cat * EE;
    const int* ei = cat == 0 ? e0 : (cat == 1 ? e1 : e2);
    atomicAdd(&g_deg[cat][ei[EE + le]], 1);
}

// ---------------- k2: CSR scan -------------------------------------------------
__global__ void scan3_kernel()
{
    const int cat = blockIdx.x;
    const int* deg = g_deg[cat];
    int* rowptr = g_rowptr[cat];
    int* cur = g_cur[cat];
    const int t = threadIdx.x;              // 0..1023
    const int CH = (NN + 1023) / 1024;      // 40
    const int lo = t * CH;
    const int hi = min(lo + CH, NN);
    int s = 0;
    for (int i = lo; i < hi; i++) s += deg[i];
    __shared__ int wsum[32];
    const int lane = t & 31, wid = t >> 5;
    int v = s;
#pragma unroll
    for (int o = 1; o < 32; o <<= 1) {
        const int u = __shfl_up_sync(0xFFFFFFFFu, v, o);
        if (lane >= o) v += u;
    }
    if (lane == 31) wsum[wid] = v;
    __syncthreads();
    if (wid == 0) {
        int u = wsum[lane];
#pragma unroll
        for (int o = 1; o < 32; o <<= 1) {
            const int t2 = __shfl_up_sync(0xFFFFFFFFu, u, o);
            if (lane >= o) u += t2;
        }
        wsum[lane] = u;
    }
    __syncthreads();
    int run = v - s + (wid ? wsum[wid - 1] : 0);
    for (int i = lo; i < hi; i++) {
        rowptr[i] = run; cur[i] = run; run += deg[i];
    }
    if (t == 1023) rowptr[NN] = run;
}

// ---------------- GEMM body: xw = x @ W + fused attention dots ---------------
template <int DIN>
__device__ __forceinline__ void gemm_body(const float* __restrict__ x,
                                          const ulonglong2* __restrict__ Wq,
                                          const float* __restrict__ att_s,
                                          const float* __restrict__ att_d,
                                          __half* __restrict__ xw,
                                          float* __restrict__ as_,
                                          float* __restrict__ ad_,
                                          int r2, int stride, float* xs,
                                          float (*redbuf)[8][2])
{
    const int c = threadIdx.x;              // 0..127 output column
    const float vs = att_s[c];
    const float vd = att_d[c];
    const int w = c >> 5;
    for (int g = r2; g < NN / 8; g += stride) {
        const int n0 = g * 8;
        __syncthreads();
        for (int i = c; i < 8 * DIN / 4; i += 128)
            reinterpret_cast<float4*>(xs)[i] =
                reinterpret_cast<const float4*>(x + n0 * DIN)[i];
        __syncthreads();
        u64 acc2[8];
#pragma unroll
        for (int r = 0; r < 8; r++) acc2[r] = 0ull;
#pragma unroll 4
        for (int k4 = 0; k4 < DIN / 4; k4++) {
            const ulonglong2 wp = Wq[k4 * 128 + c];
#pragma unroll
            for (int r = 0; r < 8; r++) {
                const ulonglong2 a =
                    *reinterpret_cast<const ulonglong2*>(&xs[r * DIN + 4 * k4]);
                ffma2(acc2[r], a.x, wp.x);
                ffma2(acc2[r], a.y, wp.y);
            }
        }
#pragma unroll
        for (int r = 0; r < 8; r++) {
            const float accr = unpack_sum(acc2[r]);
            xw[(n0 + r) * HC + c] = __float2half_rn(accr);
            float ps = accr * vs, pd = accr * vd;
#pragma unroll
            for (int o = 16; o; o >>= 1) {
                ps += __shfl_down_sync(0xFFFFFFFFu, ps, o);
                pd += __shfl_down_sync(0xFFFFFFFFu, pd, o);
            }
            if ((c & 31) == 0) { redbuf[w][r][0] = ps; redbuf[w][r][1] = pd; }
        }
        __syncthreads();
        if (c < 16) {               // c encodes (r, h)
            const int r = c >> 1, h = c & 1;
            as_[(n0 + r) * 2 + h] = redbuf[2 * h][r][0] + redbuf[2 * h + 1][r][0];
            ad_[(n0 + r) * 2 + h] = redbuf[2 * h][r][1] + redbuf[2 * h + 1][r][1];
        }
    }
}

// ---------------- k3: 3 GEMMs + CSR scatter in one heterogeneous grid ---------
__global__ void __launch_bounds__(128)
phase1_kernel(const float* __restrict__ x0, const float* __restrict__ x1,
              const float* __restrict__ x2,
              const float* __restrict__ s0, const float* __restrict__ s1,
              const float* __restrict__ s2,
              const float* __restrict__ t0, const float* __restrict__ t1,
              const float* __restrict__ t2,
              const int* __restrict__ e0, const int* __restrict__ e1,
              const int* __restrict__ e2)
{
    __shared__ __align__(16) float xs[8 * 128];
    __shared__ float redbuf[4][8][2];
    const int role = blockIdx.x % ROLES;
    const int rank = blockIdx.x / ROLES;
    if (role < 4)
        gemm_body<128>(x0, g_Wq[0], s0, t0, g_xw[0], g_as[0], g_ad[0],
                       role * RPB + rank, 4 * RPB, xs, redbuf);
    else if (role < 8)
        gemm_body<128>(x1, g_Wq[1], s1, t1, g_xw[1], g_as[1], g_ad[1],
                       (role - 4) * RPB + rank, 4 * RPB, xs, redbuf);
    else if (role < 10)
        gemm_body<64>(x2, g_Wq[2], s2, t2, g_xw[2], g_as[2], g_ad[2],
                      (role - 8) * RPB + rank, 2 * RPB, xs, redbuf);
    else {                      // scatter role: build g_srt (independent of GEMM)
        const int stride = RPB * 128;
        for (int g = rank * 128 + threadIdx.x; g < 3 * EE; g += stride) {
            const int cat = g / EE, le = g - cat * EE;
            const int* ei = cat == 0 ? e0 : (cat == 1 ? e1 : e2);
            const int pos = atomicAdd(&g_cur[cat][ei[EE + le]], 1);
            g_srt[cat][pos] = ei[le];
        }
    }
}

// ---------------- k4: fused gather + softmax + ELU + MLP (16 nodes/block) -----
__global__ void __launch_bounds__(256)
gather_mlp_kernel(const float* __restrict__ b0, const float* __restrict__ b1,
                  const float* __restrict__ b2,
                  const float* __restrict__ bc1, const float* __restrict__ Wc2,
                  const float* __restrict__ bc2, float* __restrict__ out)
{
    __shared__ __align__(16) float hs[16 * FUSED];
    __shared__ __align__(16) int4 recs[8][32];     // per-warp edge-record stage
    __shared__ float redm[8][8];
    const int tid = threadIdx.x, wid = tid >> 5, lane = tid & 31;
    const int n0 = blockIdx.x * 16;
    const int h = lane >> 4;                  // lanes 0-15 head0, 16-31 head1

    // -------- gather: each warp processes rows wid and wid+8 ------------------
    for (int cat = 0; cat < 3; cat++) {
        const float*  as_ = g_as[cat];
        const __half* xw  = g_xw[cat];
        const int*    srt = g_srt[cat];
        const float*  bias = cat == 0 ? b0 : (cat == 1 ? b1 : b2);

#pragma unroll
        for (int rep = 0; rep < 2; rep++) {
            const int row = wid + rep * 8;
            const int dst = n0 + row;

            const float2 ad2 = *reinterpret_cast<const float2*>(&g_ad[cat][dst * 2]);
            const float2 as2 = __ldg(reinterpret_cast<const float2*>(as_) + dst);
            float t0 = as2.x + ad2.x; t0 = t0 > 0.f ? t0 : 0.2f * t0;
            float t1 = as2.y + ad2.y; t1 = t1 > 0.f ? t1 : 0.2f * t1;
            const float exs0 = __expf(t0), exs1 = __expf(t1);
            float d0 = (lane == 0) ? exs0 : 0.f;
            float d1 = (lane == 0) ? exs1 : 0.f;
            const float exself = h ? exs1 : exs0;
            const uint2 sv = __ldg(reinterpret_cast<const uint2*>(
                                       xw + (size_t)dst * HC) + lane);
            float2 sa = __half22float2(*reinterpret_cast<const __half2*>(&sv.x));
            float2 sb = __half22float2(*reinterpret_cast<const __half2*>(&sv.y));
            float4 acc = make_float4(sa.x * exself, sa.y * exself,
                                     sb.x * exself, sb.y * exself);

            const int start = __ldg(&g_rowptr[cat][dst]);
            const int end   = __ldg(&g_rowptr[cat][dst + 1]);
            for (int p = start; p < end; p += 32) {
                const int n = min(32, end - p);
                const int mysrc = (lane < n) ? __ldg(srt + p + lane) : 0;
                const float2 a = __ldg(reinterpret_cast<const float2*>(as_) + mysrc);
                float u0 = a.x + ad2.x; u0 = u0 > 0.f ? u0 : 0.2f * u0;
                float u1 = a.y + ad2.y; u1 = u1 > 0.f ? u1 : 0.2f * u1;
                const float x0 = __expf(u0), x1 = __expf(u1);
                if (lane < n) { d0 += x0; d1 += x1; }
                recs[wid][lane] = make_int4(mysrc, __float_as_int(x0),
                                            __float_as_int(x1), 0);
                __syncwarp();
#pragma unroll 4
                for (int i = 0; i < n; i++) {
                    const int4 rec = recs[wid][i];     // broadcast LDS
                    const float exh = h ? __int_as_float(rec.z)
                                        : __int_as_float(rec.y);
                    const uint2 uv = __ldg(reinterpret_cast<const uint2*>(
                                               xw + (size_t)rec.x * HC) + lane);
                    float2 fa = __half22float2(
                        *reinterpret_cast<const __half2*>(&uv.x));
                    float2 fb = __half22float2(
                        *reinterpret_cast<const __half2*>(&uv.y));
                    acc.x += fa.x * exh; acc.y += fa.y * exh;
                    acc.z += fb.x * exh; acc.w += fb.y * exh;
                }
                __syncwarp();
            }
#pragma unroll
            for (int o = 16; o; o >>= 1) {
                d0 += __shfl_xor_sync(0xFFFFFFFFu, d0, o);
                d1 += __shfl_xor_sync(0xFFFFFFFFu, d1, o);
            }
            const float inv = __fdividef(1.f, h ? d1 : d0);
            const int col = lane * 4;
            float4 o;
            o.x = acc.x * inv + bias[col + 0]; o.x = o.x > 0.f ? o.x : expm1f(o.x);
            o.y = acc.y * inv + bias[col + 1]; o.y = o.y > 0.f ? o.y : expm1f(o.y);
            o.z = acc.z * inv + bias[col + 2]; o.z = o.z > 0.f ? o.z : expm1f(o.z);
            o.w = acc.w * inv + bias[col + 3]; o.w = o.w > 0.f ? o.w : expm1f(o.w);
            *reinterpret_cast<float4*>(&hs[row * FUSED + cat * HC + col]) = o;
        }
    }
    __syncthreads();

    // ---- MLP: two 128-thread groups, each full-K over its own 8 rows ---------
    const int j = tid & 127;           // hidden unit
    const int grp = tid >> 7;          // 0 -> rows 0-7, 1 -> rows 8-15
    u64 acc2[8];
#pragma unroll
    for (int r = 0; r < 8; r++) acc2[r] = 0ull;
#pragma unroll 2
    for (int k4 = 0; k4 < FUSED / 4; k4++) {
        const ulonglong2 wp = g_Wc1q[k4 * 128 + j];
#pragma unroll
        for (int r = 0; r < 8; r++) {
            const ulonglong2 a = *reinterpret_cast<const ulonglong2*>(
                &hs[(grp * 8 + r) * FUSED + 4 * k4]);
            ffma2(acc2[r], a.x, wp.x);
            ffma2(acc2[r], a.y, wp.y);
        }
    }
    const float w2c = Wc2[j];
    const float b1c = bc1[j];
#pragma unroll
    for (int r = 0; r < 8; r++) {
        float hv = unpack_sum(acc2[r]) + b1c;
        hv = fmaxf(hv, 0.f);
        float p = hv * w2c;
#pragma unroll
        for (int o = 16; o; o >>= 1) p += __shfl_down_sync(0xFFFFFFFFu, p, o);
        if (lane == 0) redm[wid][r] = p;   // wid 0-3: rows 0-7; wid 4-7: rows 8-15
    }
    __syncthreads();
    if (tid < 16) {
        const int grp2 = tid >> 3;         // which group owns this row
        const int r = tid & 7;
        const int wbase = grp2 * 4;
        out[n0 + tid] = redm[wbase + 0][r] + redm[wbase + 1][r] +
                        redm[wbase + 2][r] + redm[wbase + 3][r] + bc2[0];
    }
}

// ---------------- host orchestration ------------------------------------------
extern "C" void kernel_launch(void* const* d_in, const int* in_sizes, int n_in,
                              void* d_out, int out_size)
{
    const float* x[3];  const int* ei[3];  const float* W[3];
    const float* atts[3]; const float* attd[3]; const float* bias[3];
    for (int i = 0; i < 3; i++) {
        x[i]    = (const float*)d_in[6 * i + 0];
        ei[i]   = (const int*)  d_in[6 * i + 1];
        W[i]    = (const float*)d_in[6 * i + 2];
        atts[i] = (const float*)d_in[6 * i + 3];
        attd[i] = (const float*)d_in[6 * i + 4];
        bias[i] = (const float*)d_in[6 * i + 5];
    }
    const float* Wc1 = (const float*)d_in[18];
    const float* bc1 = (const float*)d_in[19];
    const float* Wc2 = (const float*)d_in[20];
    const float* bc2 = (const float*)d_in[21];
    float* out = (float*)d_out;

    int* p_deg;
    cudaGetSymbolAddress((void**)&p_deg, g_deg);
    cudaMemsetAsync(p_deg, 0, sizeof(int) * 3 * NN);

    // k0: pack   k1: hist   k2: scan   k3: phase1 (capture slot)   k4: gather
    pack_kernel<<<88, 256>>>(W[0], W[1], W[2], Wc1);

    hist_kernel<<<(3 * EE + 255) / 256, 256>>>(ei[0], ei[1], ei[2]);

    scan3_kernel<<<3, 1024>>>();

    phase1_kernel<<<P1GRID, 128>>>(x[0], x[1], x[2],
                                   atts[0], atts[1], atts[2],
                                   attd[0], attd[1], attd[2],
                                   ei[0], ei[1], ei[2]);

    gather_mlp_kernel<<<NN / 16, 256>>>(bias[0], bias[1], bias[2],
                                        bc1, Wc2, bc2, out);
}